// round 1
// baseline (speedup 1.0000x reference)
#include <cuda_runtime.h>
#include <cstdint>

// Embedding gather: out[i, :] = weight[index[i], :]
// weight: [1'000'000, 128] float32   (d_in[0])
// index : [2'097'152] int32          (d_in[1])
// out   : [2'097'152, 128] float32
//
// One warp per row: lane l moves float4 #l of the 128-float (512 B) row.
// Fully coalesced 128B transactions on both the gather read and the stream write.

static constexpr int D = 128;            // floats per row
static constexpr int V = D / 4;          // float4 per row = 32 = one warp

__global__ __launch_bounds__(256) void embed_gather_kernel(
    const float4* __restrict__ weight,
    const int*    __restrict__ index,
    float4*       __restrict__ out,
    int n_index)
{
    const int gtid = blockIdx.x * blockDim.x + threadIdx.x;
    const int row  = gtid >> 5;          // warp id = output row
    const int lane = gtid & 31;
    if (row >= n_index) return;

    const int src = index[row];          // uniform across warp (L1 broadcast)

    const size_t src_off = (size_t)src * V + lane;
    const size_t dst_off = (size_t)row * V + lane;
    out[dst_off] = __ldg(&weight[src_off]);
}

extern "C" void kernel_launch(void* const* d_in, const int* in_sizes, int n_in,
                              void* d_out, int out_size)
{
    const float4* weight = (const float4*)d_in[0];
    const int*    index  = (const int*)d_in[1];
    float4*       out    = (float4*)d_out;

    const int n_index = in_sizes[1];     // 2,097,152

    const int threads = 256;             // 8 warps -> 8 rows per block
    const long long total_threads = (long long)n_index * 32;
    const int blocks = (int)((total_threads + threads - 1) / threads);

    embed_gather_kernel<<<blocks, threads>>>(weight, index, out, n_index);
}

// round 2
// speedup vs baseline: 1.2477x; 1.2477x over previous
#include <cuda_runtime.h>
#include <cstdint>

// Embedding gather: out[i, :] = weight[index[i], :]
// weight: [1'000'000, 128] float32   (d_in[0])  -- 512 MB
// index : [2'097'152] int32          (d_in[1])
// out   : [2'097'152, 128] float32   -- 1 GB
//
// One warp handles R=4 rows. All 4 gather loads are issued before any store
// (MLP=4 per warp) to hide DRAM latency. Output uses write-through stores
// (__stwt) so the 1 GB streaming write does not evict weight lines from L2 —
// the index distribution has ~2.3x average reuse per distinct row, which L2
// can now capture.

static constexpr int V = 32;             // float4 per row (128 floats)
static constexpr int R = 4;              // rows per warp

__global__ __launch_bounds__(256) void embed_gather_kernel(
    const float4* __restrict__ weight,
    const int*    __restrict__ index,
    float4*       __restrict__ out,
    int n_index)
{
    const int gtid = blockIdx.x * blockDim.x + threadIdx.x;
    const int warp = gtid >> 5;
    const int lane = gtid & 31;

    const long long base = (long long)warp * R;
    if (base >= n_index) return;

    // Load the R indices (uniform per warp; L1 broadcast).
    int src[R];
#pragma unroll
    for (int r = 0; r < R; r++) {
        long long row = base + r;
        src[r] = (row < n_index) ? index[row] : 0;
    }

    // Issue all gather loads back-to-back: 4 outstanding LDG.128 per thread.
    float4 v[R];
#pragma unroll
    for (int r = 0; r < R; r++) {
        v[r] = __ldg(&weight[(size_t)src[r] * V + lane]);
    }

    // Streaming write-through stores: don't pollute L2 with the output.
#pragma unroll
    for (int r = 0; r < R; r++) {
        long long row = base + r;
        if (row < n_index) {
            __stwt(&out[(size_t)row * V + lane], v[r]);
        }
    }
}

extern "C" void kernel_launch(void* const* d_in, const int* in_sizes, int n_in,
                              void* d_out, int out_size)
{
    const float4* weight = (const float4*)d_in[0];
    const int*    index  = (const int*)d_in[1];
    float4*       out    = (float4*)d_out;

    const int n_index = in_sizes[1];     // 2,097,152

    const int threads = 256;                       // 8 warps/block
    const long long rows_per_block = 8LL * R;      // 32 rows
    const int blocks = (int)(((long long)n_index + rows_per_block - 1) / rows_per_block);

    embed_gather_kernel<<<blocks, threads>>>(weight, index, out, n_index);
}